// round 1
// baseline (speedup 1.0000x reference)
#include <cuda_runtime.h>
#include <math.h>

#define N_NODES 10000
#define K_NBR   32
#define C_DIM   64
#define H_DIM   64
#define ALPHA   0.3f

// Precomputed per-node hidden: leaky_relu(embs @ Q_w + Q_b). 2.56 MB, L2-resident.
__device__ float g_H[N_NODES * H_DIM];

__device__ __forceinline__ float leaky(float x) { return x >= 0.f ? x : ALPHA * x; }

// ---------------------------------------------------------------------------
// Kernel A: g_H[n][h] = leaky(sum_c embs[n][c] * Qw[c][h] + Qb[h])
// warp-per-node; lane handles h = lane and h = lane+32.
// ---------------------------------------------------------------------------
__global__ __launch_bounds__(512) void qproj_kernel(const float* __restrict__ embs,
                                                    const float* __restrict__ Qw,
                                                    const float* __restrict__ Qb) {
    __shared__ float2 sQ[C_DIM * 32];   // sQ[c*32+l] = (Qw[c][l], Qw[c][l+32])
    __shared__ float  sQb[H_DIM];
    __shared__ float  sE[16][C_DIM];

    const int tid  = threadIdx.x;
    const int lane = tid & 31;
    const int warp = tid >> 5;

    for (int i = tid; i < C_DIM * 32; i += 512) {
        int c = i >> 5, l = i & 31;
        sQ[i] = make_float2(Qw[c * H_DIM + l], Qw[c * H_DIM + 32 + l]);
    }
    if (tid < H_DIM) sQb[tid] = Qb[tid];
    __syncthreads();

    const int node = blockIdx.x * 16 + warp;   // grid is exact: 625*16 = 10000

    sE[warp][lane]      = embs[node * C_DIM + lane];
    sE[warp][32 + lane] = embs[node * C_DIM + 32 + lane];
    __syncwarp();

    float o0 = sQb[lane];
    float o1 = sQb[32 + lane];
#pragma unroll
    for (int c = 0; c < C_DIM; c += 4) {
        float4 x = *(const float4*)&sE[warp][c];
        float2 w;
        w = sQ[(c + 0) * 32 + lane]; o0 += x.x * w.x; o1 += x.x * w.y;
        w = sQ[(c + 1) * 32 + lane]; o0 += x.y * w.x; o1 += x.y * w.y;
        w = sQ[(c + 2) * 32 + lane]; o0 += x.z * w.x; o1 += x.z * w.y;
        w = sQ[(c + 3) * 32 + lane]; o0 += x.w * w.x; o1 += x.w * w.y;
    }
    g_H[node * H_DIM + lane]      = leaky(o0);
    g_H[node * H_DIM + 32 + lane] = leaky(o1);
}

// ---------------------------------------------------------------------------
// Kernel B: gather neighbors from g_H + weights, weighted mean, concat with
// emb, 128x64 GEMM, leaky, L2-normalize. warp-per-node.
// ---------------------------------------------------------------------------
__global__ __launch_bounds__(512) void agg_kernel(const float* __restrict__ embs,
                                                  const float* __restrict__ weights,
                                                  const int*   __restrict__ nbr,
                                                  const float* __restrict__ Ww,
                                                  const float* __restrict__ Wb,
                                                  float* __restrict__ out) {
    __shared__ float2 sW[128 * 32];     // sW[c*32+l] = (Ww[c][l], Ww[c][l+32])
    __shared__ float  sB[H_DIM];
    __shared__ float  sX[16][128];      // per-warp concat vector [emb | wsum_hidden]

    const int tid  = threadIdx.x;
    const int lane = tid & 31;
    const int warp = tid >> 5;

    for (int i = tid; i < 128 * 32; i += 512) {
        int c = i >> 5, l = i & 31;
        sW[i] = make_float2(Ww[c * H_DIM + l], Ww[c * H_DIM + 32 + l]);
    }
    if (tid < H_DIM) sB[tid] = Wb[tid];
    __syncthreads();

    const int node = blockIdx.x * 16 + warp;   // grid exact: 625*16 = 10000

    // lane k owns neighbor k
    const int   j = nbr[node * K_NBR + lane];
    const float w = weights[node * N_NODES + j];

    float wsum = w;
#pragma unroll
    for (int o = 16; o; o >>= 1) wsum += __shfl_xor_sync(0xffffffffu, wsum, o);

    float a0 = 0.f, a1 = 0.f;
#pragma unroll
    for (int k = 0; k < K_NBR; ++k) {
        const int   jk = __shfl_sync(0xffffffffu, j, k);
        const float wk = __shfl_sync(0xffffffffu, w, k);
        const float* hr = &g_H[jk * H_DIM];
        a0 += wk * hr[lane];        // coalesced 128B, L2-resident
        a1 += wk * hr[32 + lane];
    }
    const float inv = 1.f / (wsum + 1e-6f);

    sX[warp][lane]      = embs[node * C_DIM + lane];
    sX[warp][32 + lane] = embs[node * C_DIM + 32 + lane];
    sX[warp][64 + lane] = a0 * inv;
    sX[warp][96 + lane] = a1 * inv;
    __syncwarp();

    float o0 = sB[lane];
    float o1 = sB[32 + lane];
#pragma unroll
    for (int c = 0; c < 128; c += 4) {
        float4 x = *(const float4*)&sX[warp][c];
        float2 ww;
        ww = sW[(c + 0) * 32 + lane]; o0 += x.x * ww.x; o1 += x.x * ww.y;
        ww = sW[(c + 1) * 32 + lane]; o0 += x.y * ww.x; o1 += x.y * ww.y;
        ww = sW[(c + 2) * 32 + lane]; o0 += x.z * ww.x; o1 += x.z * ww.y;
        ww = sW[(c + 3) * 32 + lane]; o0 += x.w * ww.x; o1 += x.w * ww.y;
    }
    o0 = leaky(o0);
    o1 = leaky(o1);

    float ss = o0 * o0 + o1 * o1;
#pragma unroll
    for (int o = 16; o; o >>= 1) ss += __shfl_xor_sync(0xffffffffu, ss, o);
    const float d = 1.f / (sqrtf(ss) + 1e-6f);

    out[node * H_DIM + lane]      = o0 * d;
    out[node * H_DIM + 32 + lane] = o1 * d;
}

// ---------------------------------------------------------------------------
// Launch: inputs in metadata order:
//   0 embs (1,10000,64) f32   1 weights (10000,10000) f32
//   2 neighbor_set (10000,32) i32   3 Q_w (64,64) f32   4 Q_b (64,) f32
//   5 W_w (128,64) f32   6 W_b (64,) f32
// ---------------------------------------------------------------------------
extern "C" void kernel_launch(void* const* d_in, const int* in_sizes, int n_in,
                              void* d_out, int out_size) {
    const float* embs    = (const float*)d_in[0];
    const float* weights = (const float*)d_in[1];
    const int*   nbr     = (const int*)  d_in[2];
    const float* Qw      = (const float*)d_in[3];
    const float* Qb      = (const float*)d_in[4];
    const float* Ww      = (const float*)d_in[5];
    const float* Wb      = (const float*)d_in[6];
    float* out = (float*)d_out;

    qproj_kernel<<<625, 512>>>(embs, Qw, Qb);
    agg_kernel<<<625, 512>>>(embs, weights, nbr, Ww, Wb, out);
}

// round 2
// speedup vs baseline: 1.2821x; 1.2821x over previous
#include <cuda_runtime.h>
#include <math.h>

#define N_NODES 10000
#define K_NBR   32
#define C_DIM   64
#define H_DIM   64
#define ALPHA   0.3f

typedef unsigned long long u64;

// Intermediates (static device arrays, both 2.56 MB -> L2-resident):
// g_H[n][h] = leaky(embs[n] @ Q_w + Q_b)        (neighbor hidden table)
// g_P[n][h] = embs[n] @ W_top + W_b             (emb half of concat GEMM, no leaky)
__device__ float g_H[N_NODES * H_DIM];
__device__ float g_P[N_NODES * H_DIM];

__device__ __forceinline__ u64 pack2(float x) {
    u64 r; asm("mov.b64 %0, {%1, %1};" : "=l"(r) : "f"(x)); return r;
}
__device__ __forceinline__ void ffma2(u64& d, u64 a, u64 b) {
    asm("fma.rn.f32x2 %0, %1, %2, %0;" : "+l"(d) : "l"(a), "l"(b));
}
__device__ __forceinline__ float2 unpack2(u64 v) {
    float2 f; asm("mov.b64 {%0, %1}, %2;" : "=f"(f.x), "=f"(f.y) : "l"(v)); return f;
}
__device__ __forceinline__ float leaky(float x) { return x >= 0.f ? x : ALPHA * x; }

// ---------------------------------------------------------------------------
// Kernel A: per node, two 64x64 GEMMs over embs:
//   g_H = leaky(embs @ Q_w + Q_b),  g_P = embs @ W_w[0:64] + W_b
// block = 256 (8 warps), 4 nodes/warp, grid = 313 (covers 10016, clamped).
// Lane owns h = 2*lane, 2*lane+1 (float2-contiguous).
// ---------------------------------------------------------------------------
__global__ __launch_bounds__(256) void qproj_kernel(const float* __restrict__ embs,
                                                    const float* __restrict__ Qw,
                                                    const float* __restrict__ Qb,
                                                    const float* __restrict__ Ww,
                                                    const float* __restrict__ Wb) {
    __shared__ float2 sQ[C_DIM * 32];   // sQ[c*32+l] = (Qw[c][2l], Qw[c][2l+1])
    __shared__ float2 sP[C_DIM * 32];   // W_top rows 0..63 of Ww, same packing
    __shared__ float  sE[8][4][C_DIM];  // per-warp emb vectors

    const int tid  = threadIdx.x;
    const int lane = tid & 31;
    const int warp = tid >> 5;

    const float2* Q2 = (const float2*)Qw;
    const float2* W2 = (const float2*)Ww;
    for (int i = tid; i < C_DIM * 32; i += 256) { sQ[i] = Q2[i]; sP[i] = W2[i]; }
    __syncthreads();

    int rn[4];
#pragma unroll
    for (int i = 0; i < 4; ++i) {
        rn[i] = blockIdx.x * 32 + warp * 4 + i;
        int node = min(rn[i], N_NODES - 1);
        float2 e = ((const float2*)embs)[node * 32 + lane];
        *(float2*)&sE[warp][i][2 * lane] = e;
    }
    __syncwarp();

    const u64 qb = ((const u64*)Qb)[lane];
    const u64 wb = ((const u64*)Wb)[lane];
    u64 aq[4], ap[4];
#pragma unroll
    for (int i = 0; i < 4; ++i) { aq[i] = qb; ap[i] = wb; }

    const u64* sQ64 = (const u64*)sQ;
    const u64* sP64 = (const u64*)sP;
#pragma unroll
    for (int c = 0; c < C_DIM; c += 4) {
        u64 q0 = sQ64[(c + 0) * 32 + lane], p0 = sP64[(c + 0) * 32 + lane];
        u64 q1 = sQ64[(c + 1) * 32 + lane], p1 = sP64[(c + 1) * 32 + lane];
        u64 q2 = sQ64[(c + 2) * 32 + lane], p2 = sP64[(c + 2) * 32 + lane];
        u64 q3 = sQ64[(c + 3) * 32 + lane], p3 = sP64[(c + 3) * 32 + lane];
#pragma unroll
        for (int i = 0; i < 4; ++i) {
            float4 x = *(const float4*)&sE[warp][i][c];
            u64 x0 = pack2(x.x), x1 = pack2(x.y), x2 = pack2(x.z), x3 = pack2(x.w);
            ffma2(aq[i], x0, q0); ffma2(ap[i], x0, p0);
            ffma2(aq[i], x1, q1); ffma2(ap[i], x1, p1);
            ffma2(aq[i], x2, q2); ffma2(ap[i], x2, p2);
            ffma2(aq[i], x3, q3); ffma2(ap[i], x3, p3);
        }
    }

#pragma unroll
    for (int i = 0; i < 4; ++i) {
        if (rn[i] < N_NODES) {
            float2 h = unpack2(aq[i]);
            h.x = leaky(h.x); h.y = leaky(h.y);
            ((float2*)g_H)[rn[i] * 32 + lane] = h;
            ((float2*)g_P)[rn[i] * 32 + lane] = unpack2(ap[i]);
        }
    }
}

// ---------------------------------------------------------------------------
// Kernel B: gather+weighted-mean from g_H (L2-resident), then
//   out = normalize(leaky(g_P + wsh @ W_w[64:128]))
// block = 256 (8 warps), 4 nodes/warp, grid = 313.
// ---------------------------------------------------------------------------
__global__ __launch_bounds__(256) void agg_kernel(const float* __restrict__ weights,
                                                  const int*   __restrict__ nbr,
                                                  const float* __restrict__ Ww,
                                                  float* __restrict__ out) {
    __shared__ float2 sV[H_DIM * 32];   // W_bot rows 64..127, (W[c][2l], W[c][2l+1])
    __shared__ float  sX[8][4][H_DIM];  // per-warp weighted-sum-hidden vectors

    const int tid  = threadIdx.x;
    const int lane = tid & 31;
    const int warp = tid >> 5;

    const float2* W2 = (const float2*)Ww;
    for (int i = tid; i < H_DIM * 32; i += 256) sV[i] = W2[2048 + i];  // rows 64..127
    __syncthreads();

    int rn[4], nd[4], jj[4];
    float wt[4];
#pragma unroll
    for (int i = 0; i < 4; ++i) {
        rn[i] = blockIdx.x * 32 + warp * 4 + i;
        nd[i] = min(rn[i], N_NODES - 1);
        jj[i] = nbr[nd[i] * K_NBR + lane];
        wt[i] = weights[(size_t)nd[i] * N_NODES + jj[i]];   // random 4B scatter
    }

    // gather + weighted accumulate (g_H is L2-resident; 1 LDG.64 per (node,k))
    u64 acc[4] = {0, 0, 0, 0};
    const u64* H2 = (const u64*)g_H;
#pragma unroll 8
    for (int k = 0; k < K_NBR; ++k) {
#pragma unroll
        for (int i = 0; i < 4; ++i) {
            int   jk = __shfl_sync(0xffffffffu, jj[i], k);
            float wk = __shfl_sync(0xffffffffu, wt[i], k);
            ffma2(acc[i], pack2(wk), H2[jk * 32 + lane]);
        }
    }

    // weight sums + normalize the mean, stage wsh into shared for broadcast
#pragma unroll
    for (int i = 0; i < 4; ++i) {
        float ws = wt[i];
#pragma unroll
        for (int o = 16; o; o >>= 1) ws += __shfl_xor_sync(0xffffffffu, ws, o);
        float inv = 1.f / (ws + 1e-6f);
        float2 a = unpack2(acc[i]);
        a.x *= inv; a.y *= inv;
        *(float2*)&sX[warp][i][2 * lane] = a;
    }
    __syncwarp();

    // o = g_P row + wsh @ W_bot
    u64 o[4];
    const u64* P2 = (const u64*)g_P;
#pragma unroll
    for (int i = 0; i < 4; ++i) o[i] = P2[nd[i] * 32 + lane];

    const u64* sV64 = (const u64*)sV;
#pragma unroll
    for (int c = 0; c < H_DIM; c += 4) {
        u64 v0 = sV64[(c + 0) * 32 + lane];
        u64 v1 = sV64[(c + 1) * 32 + lane];
        u64 v2 = sV64[(c + 2) * 32 + lane];
        u64 v3 = sV64[(c + 3) * 32 + lane];
#pragma unroll
        for (int i = 0; i < 4; ++i) {
            float4 x = *(const float4*)&sX[warp][i][c];
            ffma2(o[i], pack2(x.x), v0);
            ffma2(o[i], pack2(x.y), v1);
            ffma2(o[i], pack2(x.z), v2);
            ffma2(o[i], pack2(x.w), v3);
        }
    }

    // leaky + L2-normalize + store
#pragma unroll
    for (int i = 0; i < 4; ++i) {
        float2 f = unpack2(o[i]);
        f.x = leaky(f.x); f.y = leaky(f.y);
        float ss = f.x * f.x + f.y * f.y;
#pragma unroll
        for (int off = 16; off; off >>= 1) ss += __shfl_xor_sync(0xffffffffu, ss, off);
        float d = 1.f / (sqrtf(ss) + 1e-6f);
        if (rn[i] < N_NODES)
            ((float2*)out)[rn[i] * 32 + lane] = make_float2(f.x * d, f.y * d);
    }
}

// ---------------------------------------------------------------------------
// Inputs (metadata order):
//   0 embs (1,10000,64) f32   1 weights (10000,10000) f32
//   2 neighbor_set (10000,32) i32   3 Q_w (64,64) f32   4 Q_b (64,) f32
//   5 W_w (128,64) f32   6 W_b (64,) f32
// ---------------------------------------------------------------------------
extern "C" void kernel_launch(void* const* d_in, const int* in_sizes, int n_in,
                              void* d_out, int out_size) {
    const float* embs    = (const float*)d_in[0];
    const float* weights = (const float*)d_in[1];
    const int*   nbr     = (const int*)  d_in[2];
    const float* Qw      = (const float*)d_in[3];
    const float* Qb      = (const float*)d_in[4];
    const float* Ww      = (const float*)d_in[5];
    const float* Wb      = (const float*)d_in[6];
    float* out = (float*)d_out;

    qproj_kernel<<<313, 256>>>(embs, Qw, Qb, Ww, Wb);
    agg_kernel<<<313, 256>>>(weights, nbr, Ww, out);
}